// round 1
// baseline (speedup 1.0000x reference)
#include <cuda_runtime.h>
#include <math.h>

// NCE loss: B=8, L=2048, E=512, V=50257, NR=100 (shared noise).
// loss = mean_t [ softplus(-x_t) + sum_j softplus(x_nj) ]
//   x = (score - log V) - logprob_noise - log NR
// Noise embeddings (100x512 f32 = 204.8KB) fit in one CTA's smem.

#define E            512
#define NRR          100      // real noise columns
#define NRP          104      // padded to multiple of 8
#define TPB          512      // 16 warps
#define TOKS_PER_BLK 128
#define GRID1        128
#define NTOK         16384

__device__ float g_partials[GRID1];

__device__ __forceinline__ float softplus_fast(float x) {
    // stable: max(x,0) + log(1 + exp(-|x|)); exact 0 for x = -inf (pad columns)
    return fmaxf(x, 0.0f) + __logf(1.0f + __expf(-fabsf(x)));
}

__global__ void __launch_bounds__(TPB, 1)
nce_main(const float* __restrict__ inp,
         const float* __restrict__ emb,
         const float* __restrict__ bias,
         const float* __restrict__ logn,
         const int*   __restrict__ target,
         const int*   __restrict__ noise_idx,
         float csub)
{
    extern __shared__ float smem[];
    float4* sN   = (float4*)smem;          // NRP rows x 128 float4 (linear layout)
    float*  sC   = smem + NRP * E;         // per-column constant
    float*  sRed = sC + NRP;               // warp partials

    const int tid = threadIdx.x;

    // ---- stage noise embeddings (gathered rows) into smem, zero-pad rows >= NR
    for (int i = tid; i < NRP * (E / 4); i += TPB) {
        int j  = i >> 7;
        int k4 = i & 127;
        float4 v = make_float4(0.f, 0.f, 0.f, 0.f);
        if (j < NRR) {
            int row = noise_idx[j];
            v = ((const float4*)(emb + (size_t)row * E))[k4];
        }
        sN[i] = v;
    }
    if (tid < NRP) {
        float c = -INFINITY;                 // pad columns contribute softplus(-inf)=0
        if (tid < NRR) {
            int nid = noise_idx[tid];
            c = bias[nid] - logn[nid] - csub;
        }
        sC[tid] = c;
    }
    __syncthreads();

    const int warp  = tid >> 5;
    const int lane  = tid & 31;
    const int slice = lane & 7;    // k-slice: [slice*64, slice*64+64)
    const int tg    = lane >> 3;   // token-in-warp (4 per warp)
    const int kbase = slice * 16;  // in float4 units

    // Per-p byte offsets into an nemb row, XOR-permuted so that at each step p
    // the 8 slices hit 8 distinct 16B bank-groups (conflict-free LDS.128).
    int boff[16];
    #pragma unroll
    for (int p = 0; p < 16; ++p) boff[p] = (kbase + (p ^ slice)) * 16;

    float myLoss = 0.0f;

    #pragma unroll 1
    for (int round = 0; round < 2; ++round) {
        int tok = blockIdx.x * TOKS_PER_BLK + round * 64 + warp * 4 + tg;

        // input slice in registers, permuted to match boff ordering
        const float4* inRow = (const float4*)(inp + (size_t)tok * E);
        float4 rin[16];
        #pragma unroll
        for (int p = 0; p < 16; ++p) rin[p] = inRow[kbase + (p ^ slice)];

        // ---- target score (gathered row, same permuted ordering)
        int tgt = target[tok];
        const float4* tRow = (const float4*)(emb + (size_t)tgt * E);
        float pt = 0.0f;
        #pragma unroll
        for (int p = 0; p < 16; ++p) {
            float4 tv = tRow[kbase + (p ^ slice)];
            pt = fmaf(rin[p].x, tv.x, pt);
            pt = fmaf(rin[p].y, tv.y, pt);
            pt = fmaf(rin[p].z, tv.z, pt);
            pt = fmaf(rin[p].w, tv.w, pt);
        }
        pt += __shfl_xor_sync(0xffffffffu, pt, 4);
        pt += __shfl_xor_sync(0xffffffffu, pt, 2);
        pt += __shfl_xor_sync(0xffffffffu, pt, 1);
        float xt = pt + bias[tgt] - logn[tgt] - csub;
        myLoss += 0.125f * softplus_fast(-xt);   // 8 slice-lanes add the same value

        // ---- noise columns, 8 at a time
        #pragma unroll 1
        for (int jg = 0; jg < NRP / 8; ++jg) {
            const char* rowbase = (const char*)sN + (size_t)jg * 8 * (E * 4);
            float v[8];
            #pragma unroll
            for (int jj = 0; jj < 8; ++jj) {
                const char* rb = rowbase + jj * (E * 4);
                float a = 0.f;
                #pragma unroll
                for (int p = 0; p < 16; ++p) {
                    float4 nv = *(const float4*)(rb + boff[p]);
                    a = fmaf(rin[p].x, nv.x, a);
                    a = fmaf(rin[p].y, nv.y, a);
                    a = fmaf(rin[p].z, nv.z, a);
                    a = fmaf(rin[p].w, nv.w, a);
                }
                v[jj] = a;
            }
            // transpose-reduce over the 8 slice lanes: lane `slice` ends with the
            // full dot of column j = jg*8 + slice (7 shfls total).
            {
                bool hi = (slice & 4) != 0;
                float s0 = hi ? v[0] : v[4];
                float s1 = hi ? v[1] : v[5];
                float s2 = hi ? v[2] : v[6];
                float s3 = hi ? v[3] : v[7];
                float r0 = __shfl_xor_sync(0xffffffffu, s0, 4);
                float r1 = __shfl_xor_sync(0xffffffffu, s1, 4);
                float r2 = __shfl_xor_sync(0xffffffffu, s2, 4);
                float r3 = __shfl_xor_sync(0xffffffffu, s3, 4);
                v[0] = (hi ? v[4] : v[0]) + r0;
                v[1] = (hi ? v[5] : v[1]) + r1;
                v[2] = (hi ? v[6] : v[2]) + r2;
                v[3] = (hi ? v[7] : v[3]) + r3;
            }
            {
                bool hi = (slice & 2) != 0;
                float s0 = hi ? v[0] : v[2];
                float s1 = hi ? v[1] : v[3];
                float r0 = __shfl_xor_sync(0xffffffffu, s0, 2);
                float r1 = __shfl_xor_sync(0xffffffffu, s1, 2);
                v[0] = (hi ? v[2] : v[0]) + r0;
                v[1] = (hi ? v[3] : v[1]) + r1;
            }
            {
                bool hi = (slice & 1) != 0;
                float s0 = hi ? v[0] : v[1];
                float r0 = __shfl_xor_sync(0xffffffffu, s0, 1);
                v[0] = (hi ? v[1] : v[0]) + r0;
            }
            float x = v[0] + sC[jg * 8 + slice];
            myLoss += softplus_fast(x);
        }
    }

    // ---- deterministic block reduction
    #pragma unroll
    for (int d = 16; d >= 1; d >>= 1)
        myLoss += __shfl_xor_sync(0xffffffffu, myLoss, d);
    if (lane == 0) sRed[warp] = myLoss;
    __syncthreads();
    if (tid == 0) {
        float s = 0.f;
        #pragma unroll
        for (int w = 0; w < 16; ++w) s += sRed[w];
        g_partials[blockIdx.x] = s;
    }
}

__global__ void nce_reduce(float* __restrict__ out) {
    int t = threadIdx.x;                 // 128 threads
    float v = g_partials[t];
    #pragma unroll
    for (int d = 16; d >= 1; d >>= 1)
        v += __shfl_xor_sync(0xffffffffu, v, d);
    __shared__ float s[4];
    if ((t & 31) == 0) s[t >> 5] = v;
    __syncthreads();
    if (t == 0) out[0] = (s[0] + s[1] + s[2] + s[3]) * (1.0f / (float)NTOK);
}

extern "C" void kernel_launch(void* const* d_in, const int* in_sizes, int n_in,
                              void* d_out, int out_size) {
    (void)in_sizes; (void)n_in; (void)out_size;
    const float* inp       = (const float*)d_in[0];
    const float* emb       = (const float*)d_in[1];
    const float* bias      = (const float*)d_in[2];
    const float* logn      = (const float*)d_in[3];
    const int*   target    = (const int*)d_in[4];
    const int*   noise_idx = (const int*)d_in[5];

    float csub = logf(50257.0f) + logf(100.0f);   // NORM_TERM + LOG_NR

    size_t smem = (size_t)(NRP * E + NRP + 32) * sizeof(float);   // ~213.5 KB
    cudaFuncSetAttribute(nce_main, cudaFuncAttributeMaxDynamicSharedMemorySize, (int)smem);

    nce_main<<<GRID1, TPB, smem>>>(inp, emb, bias, logn, target, noise_idx, csub);
    nce_reduce<<<1, 128>>>((float*)d_out);
}

// round 2
// speedup vs baseline: 2.1163x; 2.1163x over previous
#include <cuda_runtime.h>
#include <math.h>

// NCE loss: B=8, L=2048, E=512, V=50257, NR=100 (shared noise).
// loss = mean_t [ softplus(-x_t) + sum_j softplus(x_nj) ],
//   x = score - logV - logprob_noise - logNR
// Noise embeddings (104x512 f32, padded) staged in smem (~213KB, 1 CTA/SM).
// 256 thr/block: lane = k-slice of 16 floats, warp = 4 tokens/pass, Tm=4 reuse,
// packed fma.rn.f32x2, butterfly transpose-reduce.

#define E     512
#define NRR   100
#define NRP   104
#define TPB   256
#define GRID1 128
#define NTOK  16384

__device__ float g_partials[GRID1];

struct __align__(16) u64x2 { unsigned long long x, y; };

__device__ __forceinline__ unsigned long long fma2(unsigned long long a,
                                                   unsigned long long b,
                                                   unsigned long long c) {
    unsigned long long d;
    asm("fma.rn.f32x2 %0, %1, %2, %3;" : "=l"(d) : "l"(a), "l"(b), "l"(c));
    return d;
}

__device__ __forceinline__ float pairsum(unsigned long long u) {
    float lo, hi;
    asm("mov.b64 {%0, %1}, %2;" : "=f"(lo), "=f"(hi) : "l"(u));
    return lo + hi;
}

__device__ __forceinline__ float softplus_fast(float x) {
    // stable; exact 0 for x = -inf (pad columns)
    return fmaxf(x, 0.0f) + __logf(1.0f + __expf(-fabsf(x)));
}

__global__ void __launch_bounds__(TPB, 1)
nce_main(const float* __restrict__ inp,
         const float* __restrict__ emb,
         const float* __restrict__ bias,
         const float* __restrict__ logn,
         const int*   __restrict__ target,
         const int*   __restrict__ noise_idx,
         float csub)
{
    extern __shared__ float smem[];
    float4* sN   = (float4*)smem;            // NRP rows x 128 float4
    float*  sC   = smem + NRP * E;           // per-column constant
    float*  sRed = sC + NRP;                 // warp partials

    const int tid = threadIdx.x;

    // ---- stage noise embeddings; zero-pad rows >= NRR
    for (int i = tid; i < NRP * (E / 4); i += TPB) {
        int j  = i >> 7;
        int k4 = i & 127;
        float4 v = make_float4(0.f, 0.f, 0.f, 0.f);
        if (j < NRR) {
            int row = noise_idx[j];
            v = ((const float4*)(emb + (size_t)row * E))[k4];
        }
        sN[i] = v;
    }
    if (tid < NRP) {
        float c = -INFINITY;
        if (tid < NRR) {
            int nid = noise_idx[tid];
            c = bias[nid] - logn[nid] - csub;
        }
        sC[tid] = c;
    }
    __syncthreads();

    const int warp = tid >> 5;
    const int lane = tid & 31;
    const int perm = (lane >> 1) & 3;

    // byte offsets of this lane's 4 chunks within a 2KB row, XOR-permuted so
    // each LDS.128 phase (8 consecutive lanes) hits 8 distinct bank-groups
    int off16[4];
    #pragma unroll
    for (int c = 0; c < 4; ++c) off16[c] = (lane * 4 + (c ^ perm)) * 16;

    float myLoss = 0.0f;

    #pragma unroll 1
    for (int pass = 0; pass < 4; ++pass) {
        const int tokBase = blockIdx.x * 128 + pass * 32 + warp * 4;

        // ---- input slices for 4 tokens (registers, paired for f32x2)
        u64x2 rin[4][4];
        #pragma unroll
        for (int t = 0; t < 4; ++t) {
            const char* ir = (const char*)(inp + (size_t)(tokBase + t) * E);
            #pragma unroll
            for (int c = 0; c < 4; ++c)
                rin[t][c] = *(const u64x2*)(ir + off16[c]);
        }

        // ---- target scores (4 tokens)
        int   tg0 = target[tokBase + 0], tg1 = target[tokBase + 1];
        int   tg2 = target[tokBase + 2], tg3 = target[tokBase + 3];
        float tacc[4];
        {
            int tgs[4] = {tg0, tg1, tg2, tg3};
            #pragma unroll
            for (int t = 0; t < 4; ++t) {
                const char* tr = (const char*)(emb + (size_t)tgs[t] * E);
                unsigned long long a = 0ull;
                #pragma unroll
                for (int c = 0; c < 4; ++c) {
                    u64x2 tv = *(const u64x2*)(tr + off16[c]);
                    a = fma2(rin[t][c].x, tv.x, a);
                    a = fma2(rin[t][c].y, tv.y, a);
                }
                tacc[t] = pairsum(a);
            }
        }

        // ---- noise columns, 8 per group
        #pragma unroll 1
        for (int jg = 0; jg < NRP / 8; ++jg) {
            const char* gbase = (const char*)sN + (size_t)jg * 8 * (E * 4);
            unsigned long long acc[4][8];
            #pragma unroll
            for (int t = 0; t < 4; ++t)
                #pragma unroll
                for (int j = 0; j < 8; ++j) acc[t][j] = 0ull;

            #pragma unroll
            for (int c = 0; c < 4; ++c) {
                u64x2 nv[8];
                #pragma unroll
                for (int j = 0; j < 8; ++j)
                    nv[j] = *(const u64x2*)(gbase + j * (E * 4) + off16[c]);
                #pragma unroll
                for (int j = 0; j < 8; ++j) {
                    #pragma unroll
                    for (int t = 0; t < 4; ++t) {
                        acc[t][j] = fma2(rin[t][c].x, nv[j].x, acc[t][j]);
                        acc[t][j] = fma2(rin[t][c].y, nv[j].y, acc[t][j]);
                    }
                }
            }

            // collapse pairs -> 32 floats (idx = t*8 + j)
            float v[32];
            #pragma unroll
            for (int t = 0; t < 4; ++t)
                #pragma unroll
                for (int j = 0; j < 8; ++j)
                    v[t * 8 + j] = pairsum(acc[t][j]);

            // butterfly transpose-reduce over 32 lanes: lane ends with full
            // dot of (t = lane>>3, j = lane&7)
            #pragma unroll
            for (int lev = 0; lev < 5; ++lev) {
                const int d    = 16 >> lev;
                const int half = 16 >> lev;
                bool hi = (lane & d) != 0;
                #pragma unroll
                for (int i = 0; i < half; ++i) {
                    float send = hi ? v[i] : v[i + half];
                    float r = __shfl_xor_sync(0xffffffffu, send, d);
                    v[i] = (hi ? v[i + half] : v[i]) + r;
                }
            }

            float x = v[0] + sC[jg * 8 + (lane & 7)];
            myLoss += softplus_fast(x);
        }

        // ---- reduce target partials across lanes, add softplus(-x_t)
        #pragma unroll
        for (int t = 0; t < 4; ++t) {
            #pragma unroll
            for (int d = 16; d >= 1; d >>= 1)
                tacc[t] += __shfl_xor_sync(0xffffffffu, tacc[t], d);
        }
        int ts = lane >> 3;
        float tv  = (ts == 0) ? tacc[0] : (ts == 1) ? tacc[1] : (ts == 2) ? tacc[2] : tacc[3];
        int   tgt = (ts == 0) ? tg0     : (ts == 1) ? tg1     : (ts == 2) ? tg2     : tg3;
        float xt = tv + bias[tgt] - logn[tgt] - csub;
        myLoss += 0.125f * softplus_fast(-xt);   // 8 lanes duplicate each token
    }

    // ---- deterministic block reduction
    #pragma unroll
    for (int d = 16; d >= 1; d >>= 1)
        myLoss += __shfl_xor_sync(0xffffffffu, myLoss, d);
    if (lane == 0) sRed[warp] = myLoss;
    __syncthreads();
    if (tid == 0) {
        float s = 0.f;
        #pragma unroll
        for (int w = 0; w < 8; ++w) s += sRed[w];
        g_partials[blockIdx.x] = s;
    }
}

__global__ void nce_reduce(float* __restrict__ out) {
    int t = threadIdx.x;                 // 128 threads
    float v = g_partials[t];
    #pragma unroll
    for (int d = 16; d >= 1; d >>= 1)
        v += __shfl_xor_sync(0xffffffffu, v, d);
    __shared__ float s[4];
    if ((t & 31) == 0) s[t >> 5] = v;
    __syncthreads();
    if (t == 0) out[0] = (s[0] + s[1] + s[2] + s[3]) * (1.0f / (float)NTOK);
}

extern "C" void kernel_launch(void* const* d_in, const int* in_sizes, int n_in,
                              void* d_out, int out_size) {
    (void)in_sizes; (void)n_in; (void)out_size;
    const float* inp       = (const float*)d_in[0];
    const float* emb       = (const float*)d_in[1];
    const float* bias      = (const float*)d_in[2];
    const float* logn      = (const float*)d_in[3];
    const int*   target    = (const int*)d_in[4];
    const int*   noise_idx = (const int*)d_in[5];

    float csub = logf(50257.0f) + logf(100.0f);   // NORM_TERM + LOG_NR

    size_t smem = (size_t)(NRP * E + NRP + 32) * sizeof(float);   // ~213.5 KB
    cudaFuncSetAttribute(nce_main, cudaFuncAttributeMaxDynamicSharedMemorySize, (int)smem);

    nce_main<<<GRID1, TPB, smem>>>(inp, emb, bias, logn, target, noise_idx, csub);
    nce_reduce<<<1, 128>>>((float*)d_out);
}

// round 4
// speedup vs baseline: 5.5714x; 2.6327x over previous
#include <cuda_runtime.h>
#include <cuda_bf16.h>
#include <math.h>
#include <stdint.h>

// NCE loss: scores(16384x104) = inp(16384x512) @ noise_emb^T via HMMA
// (mma.sync m16n8k16 bf16 — plain sm_80+ PTX; tcgen05 not available because
// the harness emits compute_103 PTX). Plus per-token target dot in SIMT.
// Grid=128 CTAs x 256 thr; 128 tokens/CTA; B resident in smem as bf16.

#define E      512
#define NRR    100
#define NP     104          // 13 * 8, exact n-tiling
#define NT     13
#define TPB    256
#define GRID1  128
#define NTOK   16384

#define SM_B     0          // 104 rows * 1024B (512 bf16, swizzled 16B chunks)
#define SM_SC    106496     // 104 floats
#define SM_RED   106912     // 8 floats
#define SM_FLAG  106944
#define SM_TOTAL 107008

__device__ float        g_partials[GRID1];
__device__ unsigned int g_counter;

struct __align__(16) u64x2 { unsigned long long x, y; };

__device__ __forceinline__ unsigned long long fma2(unsigned long long a,
                                                   unsigned long long b,
                                                   unsigned long long c) {
    unsigned long long d;
    asm("fma.rn.f32x2 %0, %1, %2, %3;" : "=l"(d) : "l"(a), "l"(b), "l"(c));
    return d;
}
__device__ __forceinline__ float pairsum(unsigned long long u) {
    float lo, hi;
    asm("mov.b64 {%0, %1}, %2;" : "=f"(lo), "=f"(hi) : "l"(u));
    return lo + hi;
}
__device__ __forceinline__ float softplus_fast(float x) {
    return fmaxf(x, 0.0f) + __logf(1.0f + __expf(-fabsf(x)));
}
__device__ __forceinline__ uint32_t smem_u32(const void* p) {
    uint32_t a;
    asm("{ .reg .u64 t; cvta.to.shared.u64 t, %1; cvt.u32.u64 %0, t; }"
        : "=r"(a) : "l"(p));
    return a;
}
// pack two f32 -> bf16x2, lo in low half
__device__ __forceinline__ uint32_t bf2(float lo, float hi) {
    uint32_t r;
    asm("cvt.rn.bf16x2.f32 %0, %1, %2;" : "=r"(r) : "f"(hi), "f"(lo));
    return r;
}
__device__ __forceinline__ void mma16816(float* d,
        uint32_t a0, uint32_t a1, uint32_t a2, uint32_t a3,
        uint32_t b0, uint32_t b1) {
    asm volatile("mma.sync.aligned.m16n8k16.row.col.f32.bf16.bf16.f32 "
        "{%0,%1,%2,%3}, {%4,%5,%6,%7}, {%8,%9}, {%0,%1,%2,%3};"
        : "+f"(d[0]), "+f"(d[1]), "+f"(d[2]), "+f"(d[3])
        : "r"(a0), "r"(a1), "r"(a2), "r"(a3), "r"(b0), "r"(b1));
}

__global__ void __launch_bounds__(TPB, 1)
nce_hmma(const float* __restrict__ inp,
         const float* __restrict__ emb,
         const float* __restrict__ bias,
         const float* __restrict__ logn,
         const int*   __restrict__ target,
         const int*   __restrict__ noise_idx,
         float csub, float* __restrict__ out)
{
    extern __shared__ char smem[];
    const uint32_t sb = smem_u32(smem);
    const int tid = threadIdx.x, warp = tid >> 5, lane = tid & 31;
    const int gid = lane >> 2, ctg = lane & 3;
    float* sC    = (float*)(smem + SM_SC);
    float* sRed  = (float*)(smem + SM_RED);
    int*   sFlag = (int*)(smem + SM_FLAG);
    const int tokBase = blockIdx.x * 128;

    // ---- stage B: 104 x 512 bf16, n-major rows, 16B chunks XOR-swizzled
    for (int i = tid; i < NP * 64; i += TPB) {
        int n = i >> 6, c = i & 63;
        uint4 pk = make_uint4(0u, 0u, 0u, 0u);
        if (n < NRR) {
            int nid = noise_idx[n];
            const float4* r = (const float4*)(emb + (size_t)nid * E) + (c << 1);
            float4 v0 = r[0], v1 = r[1];
            pk.x = bf2(v0.x, v0.y); pk.y = bf2(v0.z, v0.w);
            pk.z = bf2(v1.x, v1.y); pk.w = bf2(v1.z, v1.w);
        }
        *(uint4*)(smem + SM_B + n * 1024 + ((c ^ (n & 7)) << 4)) = pk;
    }
    if (tid < NP) {
        float cv = -INFINITY;              // pad cols (100..103) -> softplus 0
        if (tid < NRR) {
            int nid = noise_idx[tid];
            cv = bias[nid] - logn[nid] - csub;
        }
        sC[tid] = cv;
    }
    __syncthreads();

    float myLoss = 0.0f;

    // ---- target dots: 16 tokens/warp, processed in pairs for MLP
    #pragma unroll 1
    for (int i = 0; i < 16; i += 2) {
        int t0 = tokBase + warp * 16 + i;
        int tg0 = target[t0], tg1 = target[t0 + 1];
        const u64x2* i0 = (const u64x2*)(inp + (size_t)t0 * E);
        const u64x2* i1 = (const u64x2*)(inp + (size_t)(t0 + 1) * E);
        const u64x2* e0 = (const u64x2*)(emb + (size_t)tg0 * E);
        const u64x2* e1 = (const u64x2*)(emb + (size_t)tg1 * E);
        unsigned long long A0 = 0ull, A1 = 0ull;
        #pragma unroll
        for (int q = 0; q < 4; ++q) {
            u64x2 a = i0[lane + q * 32], b = e0[lane + q * 32];
            u64x2 c = i1[lane + q * 32], d = e1[lane + q * 32];
            A0 = fma2(a.x, b.x, A0); A0 = fma2(a.y, b.y, A0);
            A1 = fma2(c.x, d.x, A1); A1 = fma2(c.y, d.y, A1);
        }
        float s0 = pairsum(A0), s1 = pairsum(A1);
        #pragma unroll
        for (int d = 16; d >= 1; d >>= 1) {
            s0 += __shfl_xor_sync(0xffffffffu, s0, d);
            s1 += __shfl_xor_sync(0xffffffffu, s1, d);
        }
        if (lane == 0) {
            myLoss += softplus_fast(-(s0 + bias[tg0] - logn[tg0] - csub));
            myLoss += softplus_fast(-(s1 + bias[tg1] - logn[tg1] - csub));
        }
    }

    // ---- GEMM: warp owns 16 token rows x all 13 n-tiles, K=512 (32 k-steps)
    float acc[NT][4];
    #pragma unroll
    for (int t = 0; t < NT; ++t)
        #pragma unroll
        for (int r = 0; r < 4; ++r) acc[t][r] = 0.0f;

    // per-lane ldmatrix params (6 x4 slots covering tiles 0..11, 1 x2 slot tile 12)
    int nb[7], m7[7];
    #pragma unroll
    for (int p = 0; p < 6; ++p) {
        int n = (2 * p + (lane >> 4)) * 8 + (lane & 7);
        nb[p] = n * 1024; m7[p] = n & 7;
    }
    { int n = 96 + (lane & 7); nb[6] = n * 1024; m7[6] = n & 7; }
    const int khB = (lane >> 3) & 1;

    const float* aR0 = inp + (size_t)(tokBase + warp * 16 + gid) * E + ctg * 2;
    const float* aR1 = aR0 + 8 * E;

    float2 f0 = *(const float2*)(aR0);
    float2 f1 = *(const float2*)(aR1);
    float2 f2 = *(const float2*)(aR0 + 8);
    float2 f3 = *(const float2*)(aR1 + 8);

    #pragma unroll 4
    for (int ks = 0; ks < 32; ++ks) {
        uint32_t a0 = bf2(f0.x, f0.y), a1 = bf2(f1.x, f1.y);
        uint32_t a2 = bf2(f2.x, f2.y), a3 = bf2(f3.x, f3.y);
        if (ks < 31) {                       // prefetch next k-step's A frag
            const float* p0 = aR0 + (ks + 1) * 16;
            const float* p1 = aR1 + (ks + 1) * 16;
            f0 = *(const float2*)(p0);     f1 = *(const float2*)(p1);
            f2 = *(const float2*)(p0 + 8); f3 = *(const float2*)(p1 + 8);
        }
        const int cb = ks * 2 + khB;
        #pragma unroll
        for (int p = 0; p < 6; ++p) {
            uint32_t b0, b1, b2, b3;
            uint32_t addr = sb + (uint32_t)(nb[p] + ((cb ^ m7[p]) << 4));
            asm volatile("ldmatrix.sync.aligned.m8n8.x4.shared.b16 "
                         "{%0,%1,%2,%3}, [%4];"
                         : "=r"(b0), "=r"(b1), "=r"(b2), "=r"(b3) : "r"(addr));
            mma16816(acc[2 * p],     a0, a1, a2, a3, b0, b1);
            mma16816(acc[2 * p + 1], a0, a1, a2, a3, b2, b3);
        }
        {
            uint32_t b0, b1;
            uint32_t addr = sb + (uint32_t)(nb[6] + ((cb ^ m7[6]) << 4));
            asm volatile("ldmatrix.sync.aligned.m8n8.x2.shared.b16 "
                         "{%0,%1}, [%2];"
                         : "=r"(b0), "=r"(b1) : "r"(addr));
            mma16816(acc[12], a0, a1, a2, a3, b0, b1);
        }
    }

    // ---- epilogue: softplus over all 128x104 scores (each exactly once)
    #pragma unroll
    for (int nt = 0; nt < NT; ++nt) {
        float c0 = sC[nt * 8 + ctg * 2];
        float c1 = sC[nt * 8 + ctg * 2 + 1];
        myLoss += softplus_fast(acc[nt][0] + c0);
        myLoss += softplus_fast(acc[nt][1] + c1);
        myLoss += softplus_fast(acc[nt][2] + c0);
        myLoss += softplus_fast(acc[nt][3] + c1);
    }

    // ---- block reduce
    #pragma unroll
    for (int d = 16; d >= 1; d >>= 1)
        myLoss += __shfl_xor_sync(0xffffffffu, myLoss, d);
    if (lane == 0) sRed[warp] = myLoss;
    __syncthreads();

    // ---- cross-block: last block reduces (single kernel, no 2nd launch)
    if (tid == 0) {
        float s = 0.f;
        #pragma unroll
        for (int w = 0; w < 8; ++w) s += sRed[w];
        g_partials[blockIdx.x] = s;
        __threadfence();
        unsigned n = atomicAdd(&g_counter, 1u);
        sFlag[0] = (n == GRID1 - 1) ? 1 : 0;
    }
    __syncthreads();
    if (sFlag[0]) {
        float v = (tid < GRID1) ? g_partials[tid] : 0.f;
        #pragma unroll
        for (int d = 16; d >= 1; d >>= 1)
            v += __shfl_xor_sync(0xffffffffu, v, d);
        if (lane == 0) sRed[warp] = v;
        __syncthreads();
        if (tid == 0) {
            float s = 0.f;
            #pragma unroll
            for (int w = 0; w < 8; ++w) s += sRed[w];
            out[0] = s * (1.0f / (float)NTOK);
            g_counter = 0u;                 // reset for next graph replay
        }
    }
}

extern "C" void kernel_launch(void* const* d_in, const int* in_sizes, int n_in,
                              void* d_out, int out_size) {
    (void)in_sizes; (void)n_in; (void)out_size;
    const float* inp       = (const float*)d_in[0];
    const float* emb       = (const float*)d_in[1];
    const float* bias      = (const float*)d_in[2];
    const float* logn      = (const float*)d_in[3];
    const int*   target    = (const int*)d_in[4];
    const int*   noise_idx = (const int*)d_in[5];

    float csub = logf(50257.0f) + logf(100.0f);   // NORM_TERM + LOG_NR

    cudaFuncSetAttribute(nce_hmma, cudaFuncAttributeMaxDynamicSharedMemorySize, SM_TOTAL);
    nce_hmma<<<GRID1, TPB, SM_TOTAL>>>(inp, emb, bias, logn, target, noise_idx,
                                       csub, (float*)d_out);
}